// round 16
// baseline (speedup 1.0000x reference)
#include <cuda_runtime.h>
#include <cuda_bf16.h>
#include <cuda_fp16.h>
#include <math.h>
#include <stdint.h>

// ---------------- problem constants ----------------
#define BB   256      // batch
#define TT   128      // time steps
#define EE   1024     // input dim
#define HH   1024     // hidden dim
#define KB1  1024     // big-GEMM K (X hi-only fp16)
#define KR   1024     // recurrence K
#define EPSF 1e-6f
#define XSC  32.0f    // pre-scale per side for fp16 (product /1024)
#define ISC2 (1.0f / (XSC * XSC))

// ---------------- scratch ----------------
__device__ __half g_Xs   [(size_t)BB * TT * KB1]; // X fp16 hi [B*T, E], x*32
__device__ __half g_WihT [(size_t)HH * KB1];      // W_ih^T fp16 hi [H, E], W*32
__device__ __half g_WhhT [(size_t)HH * KR];       // W_hh^T fp16 hi [H, H], W*32
__device__ __half g_hs   [(size_t)BB * KR];       // v fp16 [B, H] (pre-exp0 scale), v*32
__device__ float g_prem[(size_t)BB * TT * HH];    // RAW X@W_ih (true scale), all t
__device__ float g_mh  [(size_t)BB * HH];         // v @ W_hh^T (x1024 scaled), SINGLE buffer
__device__ float g_psum[8 * 16 * 32 * 5];         // per-(group,xtile,row) partial sums
__device__ float g_xn  [(size_t)BB * TT];         // ||x_t|| per row (clamped)
// per-group barriers (8 groups, cache-line separated)
__device__ unsigned g_gcnt[8 * 32];
__device__ unsigned g_ggen[8 * 32];

// ---------------- PTX helpers (sm_80-level) ----------------
__device__ __forceinline__ uint32_t smem_u32(const void* p) {
    uint32_t a;
    asm("{ .reg .u64 t; cvta.to.shared.u64 t, %1; cvt.u32.u64 %0, t; }" : "=r"(a) : "l"(p));
    return a;
}
__device__ __forceinline__ void cpasync16(uint32_t s, const void* g) {
    asm volatile("cp.async.cg.shared.global [%0], [%1], 16;" :: "r"(s), "l"(g));
}
#define CP_COMMIT() asm volatile("cp.async.commit_group;" ::: "memory")
#define CP_WAIT0()  asm volatile("cp.async.wait_group 0;" ::: "memory")
#define CP_WAIT2()  asm volatile("cp.async.wait_group 2;" ::: "memory")

__device__ __forceinline__ void ldsm_x4(uint32_t& r0, uint32_t& r1, uint32_t& r2, uint32_t& r3,
                                        uint32_t addr) {
    asm volatile("ldmatrix.sync.aligned.m8n8.x4.shared.b16 {%0,%1,%2,%3}, [%4];"
                 : "=r"(r0), "=r"(r1), "=r"(r2), "=r"(r3) : "r"(addr));
}
__device__ __forceinline__ void mma_fp16(float& d0, float& d1, float& d2, float& d3,
                                         uint32_t a0, uint32_t a1, uint32_t a2, uint32_t a3,
                                         uint32_t b0, uint32_t b1) {
    asm volatile(
        "mma.sync.aligned.m16n8k16.row.col.f32.f16.f16.f32 "
        "{%0,%1,%2,%3}, {%4,%5,%6,%7}, {%8,%9}, {%0,%1,%2,%3};"
        : "+f"(d0), "+f"(d1), "+f"(d2), "+f"(d3)
        : "r"(a0), "r"(a1), "r"(a2), "r"(a3), "r"(b0), "r"(b1));
}

// ---------------- init ----------------
__global__ void init_kernel(uint32_t* hs_u32) {
    int i = blockIdx.x * blockDim.x + threadIdx.x;
    if (i < (int)((size_t)BB * KR / 2)) hs_u32[i] = 0u;
}

// ---------------- splitX: fp16 hi of 32*x, plus ||x|| ----------------
__global__ __launch_bounds__(256) void splitX_kernel(const float* __restrict__ X,
                                                     __half* __restrict__ Xs,
                                                     float* __restrict__ xn) {
    __shared__ float sh[8];
    size_t r = blockIdx.x;
    const float* x = X + r * EE;
    __half* row = Xs + r * KB1;
    float x2 = 0.0f;
    #pragma unroll
    for (int j = 0; j < 4; j++) {
        int e = threadIdx.x + j * 256;
        float v = x[e];
        x2 += v * v;
        row[e] = __float2half_rn(v * XSC);
    }
    #pragma unroll
    for (int o = 16; o > 0; o >>= 1) x2 += __shfl_down_sync(0xffffffffu, x2, o);
    if ((threadIdx.x & 31) == 0) sh[threadIdx.x >> 5] = x2;
    __syncthreads();
    if (threadIdx.x == 0) {
        float s = 0.0f;
        #pragma unroll
        for (int w = 0; w < 8; w++) s += sh[w];
        xn[r] = fmaxf(sqrtf(s), EPSF);
    }
}

// ---------------- W [K,N] -> fp16 Wt [N, K] hi, scaled, transposed ----------
__global__ __launch_bounds__(256) void splitW_kernel(const float* __restrict__ W,
                                                     __half* __restrict__ Wt) {
    __shared__ float tile[32][33];
    int n0 = blockIdx.x * 32;
    int k0 = blockIdx.y * 32;
    int tx = threadIdx.x & 31;
    int ty = threadIdx.x >> 5;
    #pragma unroll
    for (int i = 0; i < 32; i += 8)
        tile[ty + i][tx] = W[(size_t)(k0 + ty + i) * HH + n0 + tx];
    __syncthreads();
    #pragma unroll
    for (int i = 0; i < 32; i += 8) {
        float v = tile[tx][ty + i] * XSC;
        int n = n0 + ty + i;
        int k = k0 + tx;
        Wt[(size_t)n * KB1 + k] = __float2half_rn(v);
    }
}

// ---------------- big GEMM (fp16 hi-only): prem_raw = Xs @ WihT^T / 1024 ------
__global__ void __launch_bounds__(256, 2)
big_gemm_kernel(const __half* __restrict__ A,
                const __half* __restrict__ B,
                float* __restrict__ C)
{
    constexpr int ABYTES = 128 * 128, BBYTES = 128 * 128;
    constexpr int NCH = KB1 / 64;     // 16
    extern __shared__ char smem[];
    uint32_t sbase = smem_u32(smem);
    uint32_t sA[3], sB[3];
    #pragma unroll
    for (int s = 0; s < 3; s++) {
        sA[s] = sbase + s * (ABYTES + BBYTES);
        sB[s] = sA[s] + ABYTES;
    }

    int tid  = threadIdx.x;
    int warp = tid >> 5;
    int lane = tid & 31;
    int wm = warp & 1;
    int wn = warp >> 1;

    size_t rowTile = (size_t)blockIdx.y * 128;
    size_t colTile = (size_t)blockIdx.x * 128;
    const __half* Abase = A + rowTile * KB1;
    const __half* Bbase = B + colTile * KB1;

    float acc[4][4][4];
    #pragma unroll
    for (int i = 0; i < 4; i++)
        #pragma unroll
        for (int j = 0; j < 4; j++)
            #pragma unroll
            for (int e = 0; e < 4; e++) acc[i][j][e] = 0.0f;

    auto load_stage = [&](int st, int c) {
        const __half* Ag = Abase + (size_t)c * 64;
        const __half* Bg = Bbase + (size_t)c * 64;
        #pragma unroll
        for (int u = tid; u < 128 * 8; u += 256) {
            int row = u >> 3, ch = u & 7;
            uint32_t phys = (uint32_t)(row * 128 + ((ch ^ (row & 7)) << 4));
            cpasync16(sA[st] + phys, Ag + (size_t)row * KB1 + ch * 8);
        }
        #pragma unroll
        for (int u = tid; u < 128 * 8; u += 256) {
            int row = u >> 3, ch = u & 7;
            uint32_t phys = (uint32_t)(row * 128 + ((ch ^ (row & 7)) << 4));
            cpasync16(sB[st] + phys, Bg + (size_t)row * KB1 + ch * 8);
        }
    };

    load_stage(0, 0); CP_COMMIT();
    load_stage(1, 1); CP_COMMIT();

    int st = 0;
    for (int c = 0; c < NCH; c++) {
        if (c + 2 < NCH) load_stage((st + 2) % 3, c + 2);
        CP_COMMIT();
        CP_WAIT2();
        __syncthreads();

        uint32_t a = sA[st], b = sB[st];
        #pragma unroll
        for (int s = 0; s < 4; s++) {
            uint32_t af[4][4];
            #pragma unroll
            for (int i = 0; i < 4; i++) {
                int row = wm * 64 + i * 16 + (lane & 15);
                int ch  = 2 * s + (lane >> 4);
                ldsm_x4(af[i][0], af[i][1], af[i][2], af[i][3],
                        a + row * 128 + ((ch ^ (row & 7)) << 4));
            }
            uint32_t bfm[2][4];
            #pragma unroll
            for (int j = 0; j < 2; j++) {
                int row = wn * 32 + j * 16 + (lane & 7) + ((lane >> 4) << 3);
                int ch  = 2 * s + ((lane >> 3) & 1);
                ldsm_x4(bfm[j][0], bfm[j][1], bfm[j][2], bfm[j][3],
                        b + row * 128 + ((ch ^ (row & 7)) << 4));
            }
            #pragma unroll
            for (int i = 0; i < 4; i++)
                #pragma unroll
                for (int nj = 0; nj < 4; nj++)
                    mma_fp16(acc[i][nj][0], acc[i][nj][1], acc[i][nj][2], acc[i][nj][3],
                             af[i][0], af[i][1], af[i][2], af[i][3],
                             bfm[nj >> 1][(nj & 1) * 2], bfm[nj >> 1][(nj & 1) * 2 + 1]);
        }
        __syncthreads();
        st = (st + 1) % 3;
    }

    int g = lane >> 2, t4 = lane & 3;
    #pragma unroll
    for (int i = 0; i < 4; i++)
        #pragma unroll
        for (int nj = 0; nj < 4; nj++) {
            size_t row0 = rowTile + wm * 64 + i * 16 + g;
            size_t col  = colTile + wn * 32 + nj * 8 + 2 * t4;
            *reinterpret_cast<float2*>(&C[row0 * HH + col]) =
                make_float2(acc[i][nj][0] * ISC2, acc[i][nj][1] * ISC2);
            *reinterpret_cast<float2*>(&C[(row0 + 8) * HH + col]) =
                make_float2(acc[i][nj][2] * ISC2, acc[i][nj][3] * ISC2);
        }
}

// ---------------- helpers for step math ----------------
template <int NV>
__device__ __forceinline__ void block_reduce8(float* vals, float* shbuf /* NV*8 */) {
    __syncthreads();
    #pragma unroll
    for (int v = 0; v < NV; v++) {
        float x = vals[v];
        #pragma unroll
        for (int o = 16; o > 0; o >>= 1) x += __shfl_down_sync(0xffffffffu, x, o);
        if ((threadIdx.x & 31) == 0) shbuf[v * 8 + (threadIdx.x >> 5)] = x;
    }
    __syncthreads();
    #pragma unroll
    for (int v = 0; v < NV; v++) {
        float s = 0.0f;
        #pragma unroll
        for (int w = 0; w < 8; w++) s += shbuf[v * 8 + w];
        vals[v] = s;
    }
}
__device__ __forceinline__ float artanh_clip(float x) {
    return atanhf(fminf(x, 1.0f - 1e-6f));
}

// ---------------- persistent recurrence kernel (256 thr, 128 CTAs) ----------
// Grid decode: y = bid>>4 (row band of 32), x = bid&15 (col tile of 64, FULL K).
// Resident W tile: 64 N-rows x 1024 K. A tile: 32 rows x 1024 K, reloaded per step.
// GEMM epilogue computes the 5 per-row dot-products from registers (off critical
// path); step phase only sums 16 pre-reduced slots.
#define GRP 16

__device__ __forceinline__ void group_barrier(int g) {
    __threadfence();
    __syncthreads();
    if (threadIdx.x == 0) {
        volatile unsigned* genp = &g_ggen[g * 32];
        unsigned cur = *genp;
        unsigned old = atomicAdd(&g_gcnt[g * 32], 1u);
        if (old == GRP - 1) {
            g_gcnt[g * 32] = 0;
            __threadfence();
            atomicExch(&g_ggen[g * 32], cur + 1);
        } else {
            while (*genp == cur) { }
        }
        __threadfence();
    }
    __syncthreads();
}

__global__ void __launch_bounds__(256, 1)
recurrence_kernel(const __half* __restrict__ W,        // WhhT [H, H] fp16
                  const float* __restrict__ prem,      // raw [B,T,H]
                  const float* __restrict__ bvec,      // b_h
                  const float* __restrict__ xn_arr,    // [B*T]
                  __half* __restrict__ hs,             // v fp16 [B, H]
                  float* __restrict__ mh,              // [B][H] raw v@W^T (x1024)
                  float* __restrict__ psum,            // [8][16][32][5]
                  float* __restrict__ out)             // [B,H]
{
    constexpr int NCH = 16;                 // K chunks of 64
    constexpr int CHB = 64 * 128;           // resident-B chunk bytes (64 rows x 128B)
    constexpr int ACH = 32 * 128;           // A chunk bytes (32 rows x 128B)
    extern __shared__ char smem[];
    __shared__ float wslots[8 * 32 * 5];    // per-warp per-row partials
    __shared__ float redsm[10];             // summed S[2 rows][5]
    __shared__ float redbuf[2 * 8];
    uint32_t sbase = smem_u32(smem);
    uint32_t sBres = sbase;                 // 128 KB resident B
    uint32_t sAt   = sbase + NCH * CHB;     // 64 KB A tile

    int bid  = blockIdx.x;
    int y   = bid >> 4;                     // row band (32 rows)
    int x   = bid & 15;                     // col tile (64 wide)
    int tid  = threadIdx.x;
    int warp = tid >> 5;
    int lane = tid & 31;
    int wn = warp;                          // warp n-tile: 8 cols
    int g8 = lane >> 2, t4 = lane & 3;
    int colbase = x * 64 + wn * 8 + 2 * t4;

    // resident B: W rows [x*64, +64), all K
    {
        const __half* Wb = W + (size_t)(x * 64) * KR;
        for (int u = tid; u < NCH * 64 * 8; u += 256) {
            int c   = u >> 9;               // /(64*8)
            int rm  = u & 511;
            int row = rm >> 3, ch = rm & 7;
            uint32_t phys = (uint32_t)(c * CHB + row * 128 + ((ch ^ (row & 7)) << 4));
            cpasync16(sBres + phys, Wb + (size_t)row * KR + c * 64 + ch * 8);
        }
        CP_COMMIT();
    }

    const __half* Abase = hs + (size_t)(y * 32) * KR;
    int b0 = y * 32 + x * 2;                // this CTA's step rows

    // per-thread constants
    float2 be2 = *reinterpret_cast<const float2*>(&bvec[colbase]);  // epilogue bias cols
    float4 bv4 = *reinterpret_cast<const float4*>(&bvec[tid * 4]);  // elementwise bias
    // bias^2 (step-invariant)
    float b2c;
    {
        float s = bv4.x * bv4.x + bv4.y * bv4.y + bv4.z * bv4.z + bv4.w * bv4.w;
        float v1[1] = { s };
        block_reduce8<1>(v1, redbuf);
        b2c = v1[0];
    }

    float hn_loc[2] = { EPSF, EPSF };
    float kk_prev[2] = { 1.0f, 1.0f };

    for (int t = 0; t < TT; t++) {
        // ---- A tile burst: v fp16 [32 x 1024] = 64 KB ----
        #pragma unroll 4
        for (int u = tid; u < NCH * 32 * 8; u += 256) {
            int c   = u >> 8;               // /(32*8)
            int rm  = u & 255;
            int row = rm >> 3, ch = rm & 7;
            uint32_t phys = (uint32_t)(c * ACH + row * 128 + ((ch ^ (row & 7)) << 4));
            cpasync16(sAt + phys, Abase + (size_t)row * KR + c * 64 + ch * 8);
        }
        CP_COMMIT();

        // ---- prefetch (independent of mh): epilogue prem tile + step operands
        float2 pe[2][2];
        #pragma unroll
        for (int i = 0; i < 2; i++)
            #pragma unroll
            for (int rr = 0; rr < 2; rr++) {
                int b = y * 32 + i * 16 + g8 + rr * 8;
                pe[i][rr] = *reinterpret_cast<const float2*>(
                    &prem[((size_t)b * TT + t) * HH + colbase]);
            }
        float4 p4[2]; float xnv[2];
        #pragma unroll
        for (int r = 0; r < 2; r++) {
            p4[r] = *reinterpret_cast<const float4*>(
                &prem[((size_t)(b0 + r) * TT + t) * HH + tid * 4]);
            xnv[r] = xn_arr[(size_t)(b0 + r) * TT + t];
        }

        // ---- GEMM: acc = A[32,1024] @ Bres[64,1024]^T, no intra-loop syncs ----
        float acc[2][4];
        #pragma unroll
        for (int i = 0; i < 2; i++)
            #pragma unroll
            for (int e = 0; e < 4; e++) acc[i][e] = 0.0f;

        CP_WAIT0();
        __syncthreads();

        #pragma unroll
        for (int c = 0; c < NCH; c++) {
            uint32_t a = sAt + c * ACH;
            uint32_t b = sBres + c * CHB;
            #pragma unroll
            for (int s2 = 0; s2 < 2; s2++) {
                uint32_t bf[4];
                {
                    int row = wn * 8 + (lane & 7);
                    int ch  = s2 * 4 + (lane >> 3);
                    ldsm_x4(bf[0], bf[1], bf[2], bf[3],
                            b + row * 128 + ((ch ^ (row & 7)) << 4));
                }
                #pragma unroll
                for (int sh = 0; sh < 2; sh++) {
                    int s = s2 * 2 + sh;
                    uint32_t af[2][4];
                    #pragma unroll
                    for (int i = 0; i < 2; i++) {
                        int row = i * 16 + (lane & 15);
                        int ch  = 2 * s + (lane >> 4);
                        ldsm_x4(af[i][0], af[i][1], af[i][2], af[i][3],
                                a + row * 128 + ((ch ^ (row & 7)) << 4));
                    }
                    #pragma unroll
                    for (int i = 0; i < 2; i++)
                        mma_fp16(acc[i][0], acc[i][1], acc[i][2], acc[i][3],
                                 af[i][0], af[i][1], af[i][2], af[i][3],
                                 bf[sh * 2], bf[sh * 2 + 1]);
                }
            }
        }

        // ---- epilogue: write mh tile + in-register dot-product partials ----
        #pragma unroll
        for (int i = 0; i < 2; i++) {
            #pragma unroll
            for (int rr = 0; rr < 2; rr++) {
                int row_local = i * 16 + g8 + rr * 8;
                int b = y * 32 + row_local;
                float a0 = acc[i][rr * 2], a1 = acc[i][rr * 2 + 1];
                *reinterpret_cast<float2*>(&mh[(size_t)b * HH + colbase]) =
                    make_float2(a0, a1);
                float2 p = pe[i][rr];
                float s0 = p.x * p.x + p.y * p.y;
                float s1 = p.x * a0 + p.y * a1;
                float s2 = p.x * be2.x + p.y * be2.y;
                float s3 = a0 * a0 + a1 * a1;
                float s4 = a0 * be2.x + a1 * be2.y;
                // quad-reduce (lanes sharing g8 are consecutive 4)
                #pragma unroll
                for (int o = 1; o < 4; o <<= 1) {
                    s0 += __shfl_xor_sync(0xffffffffu, s0, o);
                    s1 += __shfl_xor_sync(0xffffffffu, s1, o);
                    s2 += __shfl_xor_sync(0xffffffffu, s2, o);
                    s3 += __shfl_xor_sync(0xffffffffu, s3, o);
                    s4 += __shfl_xor_sync(0xffffffffu, s4, o);
                }
                if (t4 == 0) {
                    float* w = &wslots[(warp * 32 + row_local) * 5];
                    w[0] = s0; w[1] = s1; w[2] = s2; w[3] = s3; w[4] = s4;
                }
            }
        }
        __syncthreads();
        if (tid < 160) {                    // 32 rows x 5 sums
            float s = 0.0f;
            #pragma unroll
            for (int w = 0; w < 8; w++) s += wslots[w * 160 + tid];
            psum[((size_t)(y * 16 + x)) * 160 + tid] = s;
        }
        group_barrier(y);

        // ---- STEP phase: rows b0, b0+1 ----
        if (tid < 10) redsm[tid] = 0.0f;
        __syncthreads();
        if (tid < 160) {                    // 16 xtiles x 2 rows x 5 sums
            int xp = tid / 10;
            int rs = tid - xp * 10;
            int r  = rs / 5, s = rs - r * 5;
            float v = __ldcg(&psum[((size_t)(y * 16 + xp)) * 160 + (x * 2 + r) * 5 + s]);
            atomicAdd(&redsm[r * 5 + s], v);
        }
        __syncthreads();

        float cpr[2], cmv[2], cbr[2], ggr[2];
        #pragma unroll
        for (int r = 0; r < 2; r++) {
            float S0 = redsm[r * 5 + 0];    // p^2
            float S1 = redsm[r * 5 + 1];    // p * mh_v
            float S2 = redsm[r * 5 + 2];    // p * bias
            float S3 = redsm[r * 5 + 3];    // mh_v^2
            float S4 = redsm[r * 5 + 4];    // mh_v * bias
            float al = kk_prev[r] * ISC2;   // true-mh scale

            float mx2 = S0, mxm = al * S1, mxb = S2;
            float m2 = al * al * S3, mb = al * S4, b2 = b2c;

            float xn  = xnv[r];
            float mxn = fmaxf(sqrtf(mx2), EPSF);
            float fp  = tanhf(mxn / xn * artanh_clip(xn)) / mxn;
            float p2  = fp * fp * mx2;
            float pm  = fp * mxm;
            float pb  = fp * mxb;

            float hn  = hn_loc[r];
            float mhn = fmaxf(sqrtf(m2), EPSF);
            float fu  = tanhf(mhn / hn * artanh_clip(hn)) / mhn;
            float u2  = fu * fu * m2;
            float ub  = fu * mb;

            float den1 = fmaxf(1.0f + 2.0f * ub + u2 * b2, EPSF);
            float a1 = (1.0f + 2.0f * ub + b2) / den1;
            float c1 = (1.0f - u2) / den1;
            float hid2 = a1 * a1 * u2 + 2.0f * a1 * c1 * ub + c1 * c1 * b2;
            float ph   = a1 * fu * pm + c1 * pb;

            float den2 = fmaxf(1.0f + 2.0f * ph + p2 * hid2, EPSF);
            float q1 = (1.0f + 2.0f * ph + hid2) / den2;
            float q2 = (1.0f - p2) / den2;
            float s2v = q1 * q1 * p2 + q2 * q2 * hid2 + 2.0f * q1 * q2 * ph;
            float sn = fmaxf(sqrtf(s2v), EPSF);
            ggr[r] = artanh_clip(sn) / sn;
            cpr[r] = q1 * fp;
            cmv[r] = q2 * a1 * fu * al;     // coeff applied to raw mh_v
            cbr[r] = q2 * c1;
        }

        float v4r[2][4];
        float vv2[2] = { 0.0f, 0.0f };
        #pragma unroll
        for (int r = 0; r < 2; r++) {
            int b = b0 + r;
            float4 m4 = __ldcg(reinterpret_cast<const float4*>(&mh[(size_t)b * HH + tid * 4]));
            float sv0 = cpr[r] * p4[r].x + cmv[r] * m4.x + cbr[r] * bv4.x;
            float sv1 = cpr[r] * p4[r].y + cmv[r] * m4.y + cbr[r] * bv4.y;
            float sv2 = cpr[r] * p4[r].z + cmv[r] * m4.z + cbr[r] * bv4.z;
            float sv3 = cpr[r] * p4[r].w + cmv[r] * m4.w + cbr[r] * bv4.w;
            float v0 = tanhf(ggr[r] * sv0);
            float v1 = tanhf(ggr[r] * sv1);
            float v2 = tanhf(ggr[r] * sv2);
            float v3 = tanhf(ggr[r] * sv3);
            v4r[r][0] = v0; v4r[r][1] = v1; v4r[r][2] = v2; v4r[r][3] = v3;
            vv2[r] = v0 * v0 + v1 * v1 + v2 * v2 + v3 * v3;
        }
        block_reduce8<2>(vv2, redbuf);

        #pragma unroll
        for (int r = 0; r < 2; r++) {
            int b = b0 + r;
            float vn = fmaxf(sqrtf(vv2[r]), EPSF);
            float kk = tanhf(vn) / vn;
            // store v (NOT h) scaled for fp16; kk folded into next step via al
            __half2 h01 = __floats2half2_rn(v4r[r][0] * XSC, v4r[r][1] * XSC);
            __half2 h23 = __floats2half2_rn(v4r[r][2] * XSC, v4r[r][3] * XSC);
            uint2 pk;
            pk.x = *reinterpret_cast<uint32_t*>(&h01);
            pk.y = *reinterpret_cast<uint32_t*>(&h23);
            *reinterpret_cast<uint2*>(&hs[(size_t)b * KR + tid * 4]) = pk;
            if (t == TT - 1) {
                float4 o4 = make_float4(kk * v4r[r][0], kk * v4r[r][1],
                                        kk * v4r[r][2], kk * v4r[r][3]);
                *reinterpret_cast<float4*>(&out[(size_t)b * HH + tid * 4]) = o4;
            }
            kk_prev[r] = kk;
            hn_loc[r] = fmaxf(tanhf(vn), EPSF);
        }
        group_barrier(y);
    }
}

// ---------------- launch ----------------
extern "C" void kernel_launch(void* const* d_in, const int* in_sizes, int n_in,
                              void* d_out, int out_size)
{
    const float* inp  = (const float*)d_in[0];   // [B,T,E]
    const float* W_ih = (const float*)d_in[1];   // [E,H]
    const float* W_hh = (const float*)d_in[2];   // [H,H]
    const float* b_h  = (const float*)d_in[3];   // [H]
    float* out = (float*)d_out;                  // [B,H]

    __half *Xs, *WihT, *WhhT, *hs;
    float *prem, *mh, *xn, *psum;
    cudaGetSymbolAddress((void**)&Xs,   g_Xs);
    cudaGetSymbolAddress((void**)&WihT, g_WihT);
    cudaGetSymbolAddress((void**)&WhhT, g_WhhT);
    cudaGetSymbolAddress((void**)&hs,   g_hs);
    cudaGetSymbolAddress((void**)&prem, g_prem);
    cudaGetSymbolAddress((void**)&mh,   g_mh);
    cudaGetSymbolAddress((void**)&xn,   g_xn);
    cudaGetSymbolAddress((void**)&psum, g_psum);

    const int SMEM_BIG = 3 * (128 + 128) * 128;            // 96 KB (3 stages)
    const int SMEM_REC = 16 * 64 * 128 + 16 * 32 * 128;    // 128KB + 64KB = 192 KB
    cudaFuncSetAttribute(big_gemm_kernel,
                         cudaFuncAttributeMaxDynamicSharedMemorySize, SMEM_BIG);
    cudaFuncSetAttribute(recurrence_kernel,
                         cudaFuncAttributeMaxDynamicSharedMemorySize, SMEM_REC);

    // init hidden v = 0
    {
        int n = (int)((size_t)BB * KR / 2);
        init_kernel<<<(n + 255) / 256, 256>>>((uint32_t*)hs);
    }

    // prep: weight transposes + X scale/norms (all hi-only fp16)
    {
        dim3 gw(HH / 32, HH / 32);
        splitW_kernel<<<gw, 256>>>(W_ih, WihT);
        splitW_kernel<<<gw, 256>>>(W_hh, WhhT);
        splitX_kernel<<<BB * TT, 256>>>(inp, Xs, xn);
    }

    // big GEMM: raw prem = Xs @ WihT^T  [32768, 1024], K=1024
    {
        dim3 grid(HH / 128, (BB * TT) / 128);
        big_gemm_kernel<<<grid, 256, SMEM_BIG>>>(Xs, WihT, prem);
    }

    // persistent recurrence: one kernel for all 128 steps
    recurrence_kernel<<<128, 256, SMEM_REC>>>(WhhT, prem, b_h, xn, hs, mh, psum, out);
}

// round 17
// speedup vs baseline: 1.2463x; 1.2463x over previous
#include <cuda_runtime.h>
#include <cuda_bf16.h>
#include <cuda_fp16.h>
#include <math.h>
#include <stdint.h>

// ---------------- problem constants ----------------
#define BB   256      // batch
#define TT   128      // time steps
#define EE   1024     // input dim
#define HH   1024     // hidden dim
#define KB1  1024     // big-GEMM K (X hi-only fp16)
#define KR   1024     // recurrence K (h hi-only fp16)
#define EPSF 1e-6f
#define XSC  32.0f    // pre-scale per side for fp16 (product /1024)
#define ISC2 (1.0f / (XSC * XSC))

// ---------------- scratch ----------------
__device__ __half g_Xs   [(size_t)BB * TT * KB1]; // X fp16 hi [B*T, E], x*32
__device__ __half g_WihT [(size_t)HH * KB1];      // W_ih^T fp16 hi [H, E], W*32
__device__ __half g_WhhT [(size_t)HH * KR];       // W_hh^T fp16 hi [H, H], W*32
__device__ __half g_hs   [(size_t)BB * KR];       // h fp16 hi [B, H], h*32
__device__ float g_prem[(size_t)BB * TT * HH];    // RAW X@W_ih (true scale), all t
__device__ float g_mh  [2 * (size_t)BB * HH];     // 2 split-K partials (scaled x1024)
__device__ float g_xn  [(size_t)BB * TT];         // ||x_t|| per row (clamped)
// per-group barriers (8 groups, cache-line separated)
__device__ unsigned g_gcnt[8 * 32];
__device__ unsigned g_ggen[8 * 32];

// ---------------- PTX helpers (sm_80-level) ----------------
__device__ __forceinline__ uint32_t smem_u32(const void* p) {
    uint32_t a;
    asm("{ .reg .u64 t; cvta.to.shared.u64 t, %1; cvt.u32.u64 %0, t; }" : "=r"(a) : "l"(p));
    return a;
}
__device__ __forceinline__ void cpasync16(uint32_t s, const void* g) {
    asm volatile("cp.async.cg.shared.global [%0], [%1], 16;" :: "r"(s), "l"(g));
}
#define CP_COMMIT() asm volatile("cp.async.commit_group;" ::: "memory")
#define CP_WAIT0()  asm volatile("cp.async.wait_group 0;" ::: "memory")
#define CP_WAIT2()  asm volatile("cp.async.wait_group 2;" ::: "memory")

__device__ __forceinline__ void ldsm_x4(uint32_t& r0, uint32_t& r1, uint32_t& r2, uint32_t& r3,
                                        uint32_t addr) {
    asm volatile("ldmatrix.sync.aligned.m8n8.x4.shared.b16 {%0,%1,%2,%3}, [%4];"
                 : "=r"(r0), "=r"(r1), "=r"(r2), "=r"(r3) : "r"(addr));
}
__device__ __forceinline__ void mma_fp16(float& d0, float& d1, float& d2, float& d3,
                                         uint32_t a0, uint32_t a1, uint32_t a2, uint32_t a3,
                                         uint32_t b0, uint32_t b1) {
    asm volatile(
        "mma.sync.aligned.m16n8k16.row.col.f32.f16.f16.f32 "
        "{%0,%1,%2,%3}, {%4,%5,%6,%7}, {%8,%9}, {%0,%1,%2,%3};"
        : "+f"(d0), "+f"(d1), "+f"(d2), "+f"(d3)
        : "r"(a0), "r"(a1), "r"(a2), "r"(a3), "r"(b0), "r"(b1));
}

// ---------------- fast transcendentals (MUFU-based, rel err ~1e-6 here) ------
__device__ __forceinline__ float fast_tanh(float x) {
    float e = __expf(2.0f * x);
    return __fdividef(e - 1.0f, e + 1.0f);
}
__device__ __forceinline__ float fast_artanh_clip(float x) {  // x >= 0
    x = fminf(x, 1.0f - 1e-6f);
    return 0.5f * __logf(__fdividef(1.0f + x, 1.0f - x));
}

// ---------------- init ----------------
__global__ void init_kernel(uint32_t* hs_u32) {
    int i = blockIdx.x * blockDim.x + threadIdx.x;
    if (i < (int)((size_t)BB * KR / 2)) hs_u32[i] = 0u;
}

// ---------------- splitX: fp16 hi of 32*x, plus ||x|| ----------------
__global__ __launch_bounds__(256) void splitX_kernel(const float* __restrict__ X,
                                                     __half* __restrict__ Xs,
                                                     float* __restrict__ xn) {
    __shared__ float sh[8];
    size_t r = blockIdx.x;
    const float* x = X + r * EE;
    __half* row = Xs + r * KB1;
    float x2 = 0.0f;
    #pragma unroll
    for (int j = 0; j < 4; j++) {
        int e = threadIdx.x + j * 256;
        float v = x[e];
        x2 += v * v;
        row[e] = __float2half_rn(v * XSC);
    }
    #pragma unroll
    for (int o = 16; o > 0; o >>= 1) x2 += __shfl_down_sync(0xffffffffu, x2, o);
    if ((threadIdx.x & 31) == 0) sh[threadIdx.x >> 5] = x2;
    __syncthreads();
    if (threadIdx.x == 0) {
        float s = 0.0f;
        #pragma unroll
        for (int w = 0; w < 8; w++) s += sh[w];
        xn[r] = fmaxf(sqrtf(s), EPSF);
    }
}

// ---------------- W [K,N] -> fp16 Wt [N, K] hi, scaled, transposed ----------
__global__ __launch_bounds__(256) void splitW_kernel(const float* __restrict__ W,
                                                     __half* __restrict__ Wt) {
    __shared__ float tile[32][33];
    int n0 = blockIdx.x * 32;
    int k0 = blockIdx.y * 32;
    int tx = threadIdx.x & 31;
    int ty = threadIdx.x >> 5;
    #pragma unroll
    for (int i = 0; i < 32; i += 8)
        tile[ty + i][tx] = W[(size_t)(k0 + ty + i) * HH + n0 + tx];
    __syncthreads();
    #pragma unroll
    for (int i = 0; i < 32; i += 8) {
        float v = tile[tx][ty + i] * XSC;
        int n = n0 + ty + i;
        int k = k0 + tx;
        Wt[(size_t)n * KB1 + k] = __float2half_rn(v);
    }
}

// ---------------- big GEMM (fp16 hi-only): prem_raw = Xs @ WihT^T / 1024 ------
__global__ void __launch_bounds__(256, 2)
big_gemm_kernel(const __half* __restrict__ A,
                const __half* __restrict__ B,
                float* __restrict__ C)
{
    constexpr int ABYTES = 128 * 128, BBYTES = 128 * 128;
    constexpr int NCH = KB1 / 64;     // 16
    extern __shared__ char smem[];
    uint32_t sbase = smem_u32(smem);
    uint32_t sA[3], sB[3];
    #pragma unroll
    for (int s = 0; s < 3; s++) {
        sA[s] = sbase + s * (ABYTES + BBYTES);
        sB[s] = sA[s] + ABYTES;
    }

    int tid  = threadIdx.x;
    int warp = tid >> 5;
    int lane = tid & 31;
    int wm = warp & 1;
    int wn = warp >> 1;

    size_t rowTile = (size_t)blockIdx.y * 128;
    size_t colTile = (size_t)blockIdx.x * 128;
    const __half* Abase = A + rowTile * KB1;
    const __half* Bbase = B + colTile * KB1;

    float acc[4][4][4];
    #pragma unroll
    for (int i = 0; i < 4; i++)
        #pragma unroll
        for (int j = 0; j < 4; j++)
            #pragma unroll
            for (int e = 0; e < 4; e++) acc[i][j][e] = 0.0f;

    auto load_stage = [&](int st, int c) {
        const __half* Ag = Abase + (size_t)c * 64;
        const __half* Bg = Bbase + (size_t)c * 64;
        #pragma unroll
        for (int u = tid; u < 128 * 8; u += 256) {
            int row = u >> 3, ch = u & 7;
            uint32_t phys = (uint32_t)(row * 128 + ((ch ^ (row & 7)) << 4));
            cpasync16(sA[st] + phys, Ag + (size_t)row * KB1 + ch * 8);
        }
        #pragma unroll
        for (int u = tid; u < 128 * 8; u += 256) {
            int row = u >> 3, ch = u & 7;
            uint32_t phys = (uint32_t)(row * 128 + ((ch ^ (row & 7)) << 4));
            cpasync16(sB[st] + phys, Bg + (size_t)row * KB1 + ch * 8);
        }
    };

    load_stage(0, 0); CP_COMMIT();
    load_stage(1, 1); CP_COMMIT();

    int st = 0;
    for (int c = 0; c < NCH; c++) {
        if (c + 2 < NCH) load_stage((st + 2) % 3, c + 2);
        CP_COMMIT();
        CP_WAIT2();
        __syncthreads();

        uint32_t a = sA[st], b = sB[st];
        #pragma unroll
        for (int s = 0; s < 4; s++) {
            uint32_t af[4][4];
            #pragma unroll
            for (int i = 0; i < 4; i++) {
                int row = wm * 64 + i * 16 + (lane & 15);
                int ch  = 2 * s + (lane >> 4);
                ldsm_x4(af[i][0], af[i][1], af[i][2], af[i][3],
                        a + row * 128 + ((ch ^ (row & 7)) << 4));
            }
            uint32_t bfm[2][4];
            #pragma unroll
            for (int j = 0; j < 2; j++) {
                int row = wn * 32 + j * 16 + (lane & 7) + ((lane >> 4) << 3);
                int ch  = 2 * s + ((lane >> 3) & 1);
                ldsm_x4(bfm[j][0], bfm[j][1], bfm[j][2], bfm[j][3],
                        b + row * 128 + ((ch ^ (row & 7)) << 4));
            }
            #pragma unroll
            for (int i = 0; i < 4; i++)
                #pragma unroll
                for (int nj = 0; nj < 4; nj++)
                    mma_fp16(acc[i][nj][0], acc[i][nj][1], acc[i][nj][2], acc[i][nj][3],
                             af[i][0], af[i][1], af[i][2], af[i][3],
                             bfm[nj >> 1][(nj & 1) * 2], bfm[nj >> 1][(nj & 1) * 2 + 1]);
        }
        __syncthreads();
        st = (st + 1) % 3;
    }

    int g = lane >> 2, t4 = lane & 3;
    #pragma unroll
    for (int i = 0; i < 4; i++)
        #pragma unroll
        for (int nj = 0; nj < 4; nj++) {
            size_t row0 = rowTile + wm * 64 + i * 16 + g;
            size_t col  = colTile + wn * 32 + nj * 8 + 2 * t4;
            *reinterpret_cast<float2*>(&C[row0 * HH + col]) =
                make_float2(acc[i][nj][0] * ISC2, acc[i][nj][1] * ISC2);
            *reinterpret_cast<float2*>(&C[(row0 + 8) * HH + col]) =
                make_float2(acc[i][nj][2] * ISC2, acc[i][nj][3] * ISC2);
        }
}

// ---------------- helpers for step math ----------------
template <int NV>
__device__ __forceinline__ void block_reduce8(float* vals, float* shbuf /* NV*8 */) {
    __syncthreads();
    #pragma unroll
    for (int v = 0; v < NV; v++) {
        float x = vals[v];
        #pragma unroll
        for (int o = 16; o > 0; o >>= 1) x += __shfl_down_sync(0xffffffffu, x, o);
        if ((threadIdx.x & 31) == 0) shbuf[v * 8 + (threadIdx.x >> 5)] = x;
    }
    __syncthreads();
    #pragma unroll
    for (int v = 0; v < NV; v++) {
        float s = 0.0f;
        #pragma unroll
        for (int w = 0; w < 8; w++) s += shbuf[v * 8 + w];
        vals[v] = s;
    }
}

// ---------------- persistent recurrence kernel (256 thr, 128 CTAs) ----------
// Grid decode: y = bid>>4 (row band of 32), rem = bid&15, x = rem>>1 (col tile
// of 128), z = rem&1 (K half of 512). Only the 16 CTAs of a y-group couple.
#define GRP 16

__device__ __forceinline__ void group_barrier(int g) {
    __threadfence();
    __syncthreads();
    if (threadIdx.x == 0) {
        volatile unsigned* genp = &g_ggen[g * 32];
        unsigned cur = *genp;
        unsigned old = atomicAdd(&g_gcnt[g * 32], 1u);
        if (old == GRP - 1) {
            g_gcnt[g * 32] = 0;
            __threadfence();
            atomicExch(&g_ggen[g * 32], cur + 1);
        } else {
            while (*genp == cur) { }
        }
        __threadfence();
    }
    __syncthreads();
}

__global__ void __launch_bounds__(256, 1)
recurrence_kernel(const __half* __restrict__ W,        // WhhT [H, H] fp16 hi
                  const float* __restrict__ prem,      // raw [B,T,H]
                  const float* __restrict__ bvec,      // b_h
                  const float* __restrict__ xn_arr,    // [B*T]
                  __half* __restrict__ hs,             // [B, H] fp16 hi
                  float* __restrict__ mh,              // [2][B][H] (x1024 scaled)
                  float* __restrict__ out)             // [B,H]
{
    constexpr int BCH = 8;                  // 8 chunks of 64 = 512 K-half
    constexpr int CHB = 128 * 128;          // bytes per resident-B chunk (128 rows x 128B)
    constexpr int ACH = 32 * 128;           // bytes per A chunk (32 rows x 128B)
    extern __shared__ char smem[];
    __shared__ float redbuf[10 * 8];
    uint32_t sbase = smem_u32(smem);
    uint32_t sBres = sbase;                 // 128 KB resident B
    uint32_t sAt   = sbase + BCH * CHB;     // 32 KB whole A tile (8 chunks)

    int bid  = blockIdx.x;
    int y   = bid >> 4;                     // row band (32 rows)
    int rem = bid & 15;
    int x   = rem >> 1;                     // col tile (128 wide)
    int z   = rem & 1;                      // K half (512 wide)
    int tid  = threadIdx.x;
    int warp = tid >> 5;
    int lane = tid & 31;
    int wn = warp;                          // 8 warps across N: WARP_N = 16, NT8 = 2

    // resident B: rows [x*128, +128) of W, K [z*512, +512)
    {
        const __half* Wb = W + (size_t)(x * 128) * KR + (size_t)z * 512;
        for (int u = tid; u < BCH * 128 * 8; u += 256) {
            int c   = u / (128 * 8);
            int rm  = u - c * (128 * 8);
            int row = rm >> 3, ch = rm & 7;
            uint32_t phys = (uint32_t)(c * CHB + row * 128 + ((ch ^ (row & 7)) << 4));
            cpasync16(sBres + phys, Wb + (size_t)row * KR + c * 64 + ch * 8);
        }
        CP_COMMIT();
    }

    const __half* Abase = hs + (size_t)(y * 32) * KR;
    float* mhz = mh + (size_t)z * BB * HH;
    int koff0 = z * 512;

    float hn_loc[2] = { EPSF, EPSF };
    int b0 = y * 32 + rem * 2;              // step rows b0, b0+1 (inside band y)

    // bias (constant across steps) + bias^2 (precomputed once)
    float4 bv4 = *reinterpret_cast<const float4*>(&bvec[tid * 4]);
    float b2c;
    {
        float v1[1] = { bv4.x * bv4.x + bv4.y * bv4.y + bv4.z * bv4.z + bv4.w * bv4.w };
        block_reduce8<1>(v1, redbuf);
        b2c = v1[0];
    }

    for (int t = 0; t < TT; t++) {
        // load WHOLE A tile (32 rows x 512 k = 32 KB) in one burst
        #pragma unroll
        for (int u = tid; u < BCH * 32 * 8; u += 256) {
            int c   = u >> 8;               // /(32*8)
            int rm  = u & 255;
            int row = rm >> 3, ch = rm & 7;
            uint32_t phys = (uint32_t)(c * ACH + row * 128 + ((ch ^ (row & 7)) << 4));
            cpasync16(sAt + phys, Abase + (size_t)row * KR + koff0 + c * 64 + ch * 8);
        }
        CP_COMMIT();

        // prefetch step-phase operands independent of mh (overlap with A load)
        float4 p4[2]; float xnv[2];
        #pragma unroll
        for (int r = 0; r < 2; r++) {
            p4[r] = *reinterpret_cast<const float4*>(
                &prem[((size_t)(b0 + r) * TT + t) * HH + tid * 4]);
            xnv[r] = xn_arr[(size_t)(b0 + r) * TT + t];
        }

        // ===== GEMM phase: mh[z] tile (rows y*32..+32, cols x*128..+128) =====
        float acc[2][2][4];
        #pragma unroll
        for (int i = 0; i < 2; i++)
            #pragma unroll
            for (int j = 0; j < 2; j++)
                #pragma unroll
                for (int e = 0; e < 4; e++) acc[i][j][e] = 0.0f;

        CP_WAIT0();
        __syncthreads();

        #pragma unroll
        for (int c = 0; c < BCH; c++) {
            uint32_t a = sAt + c * ACH;
            uint32_t b = sBres + c * CHB;
            #pragma unroll
            for (int s = 0; s < 4; s++) {
                uint32_t af[2][4];
                #pragma unroll
                for (int i = 0; i < 2; i++) {
                    int row = i * 16 + (lane & 15);
                    int ch  = 2 * s + (lane >> 4);
                    ldsm_x4(af[i][0], af[i][1], af[i][2], af[i][3],
                            a + row * 128 + ((ch ^ (row & 7)) << 4));
                }
                uint32_t bfm[4];
                {
                    int row = wn * 16 + (lane & 7) + ((lane >> 4) << 3);
                    int ch  = 2 * s + ((lane >> 3) & 1);
                    ldsm_x4(bfm[0], bfm[1], bfm[2], bfm[3],
                            b + row * 128 + ((ch ^ (row & 7)) << 4));
                }
                #pragma unroll
                for (int i = 0; i < 2; i++)
                    #pragma unroll
                    for (int nj = 0; nj < 2; nj++)
                        mma_fp16(acc[i][nj][0], acc[i][nj][1], acc[i][nj][2], acc[i][nj][3],
                                 af[i][0], af[i][1], af[i][2], af[i][3],
                                 bfm[nj * 2], bfm[nj * 2 + 1]);
            }
        }

        // epilogue -> mh[z] (x1024 scaled; step divides)
        {
            int g = lane >> 2, t4 = lane & 3;
            #pragma unroll
            for (int i = 0; i < 2; i++)
                #pragma unroll
                for (int nj = 0; nj < 2; nj++) {
                    size_t row0 = (size_t)(y * 32 + i * 16 + g);
                    size_t col  = (size_t)(x * 128 + wn * 16 + nj * 8 + 2 * t4);
                    *reinterpret_cast<float2*>(&mhz[row0 * HH + col]) =
                        make_float2(acc[i][nj][0], acc[i][nj][1]);
                    *reinterpret_cast<float2*>(&mhz[(row0 + 8) * HH + col]) =
                        make_float2(acc[i][nj][2], acc[i][nj][3]);
                }
        }
        group_barrier(y);

        // ===== STEP phase: rows b0, b0+1 — fused dual-row reductions =====
        float4 m4r[2];
        float vals[10];
        #pragma unroll
        for (int r = 0; r < 2; r++) {
            int b = b0 + r;
            float4 ma = __ldcv(reinterpret_cast<const float4*>(&mh[(size_t)b * HH + tid * 4]));
            float4 mb = __ldcv(reinterpret_cast<const float4*>(
                &mh[(size_t)BB * HH + (size_t)b * HH + tid * 4]));
            float4 mv;
            mv.x = (ma.x + mb.x) * ISC2;
            mv.y = (ma.y + mb.y) * ISC2;
            mv.z = (ma.z + mb.z) * ISC2;
            mv.w = (ma.w + mb.w) * ISC2;
            m4r[r] = mv;
            float4 pv = p4[r];
            vals[r * 5 + 0] = pv.x * pv.x + pv.y * pv.y + pv.z * pv.z + pv.w * pv.w;
            vals[r * 5 + 1] = pv.x * mv.x + pv.y * mv.y + pv.z * mv.z + pv.w * mv.w;
            vals[r * 5 + 2] = pv.x * bv4.x + pv.y * bv4.y + pv.z * bv4.z + pv.w * bv4.w;
            vals[r * 5 + 3] = mv.x * mv.x + mv.y * mv.y + mv.z * mv.z + mv.w * mv.w;
            vals[r * 5 + 4] = mv.x * bv4.x + mv.y * bv4.y + mv.z * bv4.z + mv.w * bv4.w;
        }
        block_reduce8<10>(vals, redbuf);

        float cpr[2], cmr[2], cbr[2], ggr[2];
        #pragma unroll
        for (int r = 0; r < 2; r++) {
            float mx2 = vals[r * 5 + 0], mxm = vals[r * 5 + 1], mxb = vals[r * 5 + 2];
            float m2  = vals[r * 5 + 3], mb  = vals[r * 5 + 4], b2  = b2c;

            float xn  = xnv[r];
            float mxn = fmaxf(sqrtf(mx2), EPSF);
            float fp  = fast_tanh(mxn / xn * fast_artanh_clip(xn)) / mxn;
            float p2  = fp * fp * mx2;
            float pm  = fp * mxm;
            float pb  = fp * mxb;

            float hn  = hn_loc[r];
            float mhn = fmaxf(sqrtf(m2), EPSF);
            float fu  = fast_tanh(mhn / hn * fast_artanh_clip(hn)) / mhn;
            float u2  = fu * fu * m2;
            float ub  = fu * mb;

            float den1 = fmaxf(1.0f + 2.0f * ub + u2 * b2, EPSF);
            float a1 = (1.0f + 2.0f * ub + b2) / den1;
            float c1 = (1.0f - u2) / den1;
            float hid2 = a1 * a1 * u2 + 2.0f * a1 * c1 * ub + c1 * c1 * b2;
            float ph   = a1 * fu * pm + c1 * pb;

            float den2 = fmaxf(1.0f + 2.0f * ph + p2 * hid2, EPSF);
            float q1 = (1.0f + 2.0f * ph + hid2) / den2;
            float q2 = (1.0f - p2) / den2;
            float s2 = q1 * q1 * p2 + q2 * q2 * hid2 + 2.0f * q1 * q2 * ph;
            float sn = fmaxf(sqrtf(s2), EPSF);
            ggr[r] = fast_artanh_clip(sn) / sn;
            cpr[r] = q1 * fp;
            cmr[r] = q2 * a1 * fu;
            cbr[r] = q2 * c1;
        }

        float v4r[2][4];
        float vv2[2] = { 0.0f, 0.0f };
        #pragma unroll
        for (int r = 0; r < 2; r++) {
            float4 pv = p4[r], mv = m4r[r];
            float v0 = fast_tanh(ggr[r] * (cpr[r] * pv.x + cmr[r] * mv.x + cbr[r] * bv4.x));
            float v1 = fast_tanh(ggr[r] * (cpr[r] * pv.y + cmr[r] * mv.y + cbr[r] * bv4.y));
            float v2 = fast_tanh(ggr[r] * (cpr[r] * pv.z + cmr[r] * mv.z + cbr[r] * bv4.z));
            float v3 = fast_tanh(ggr[r] * (cpr[r] * pv.w + cmr[r] * mv.w + cbr[r] * bv4.w));
            v4r[r][0] = v0; v4r[r][1] = v1; v4r[r][2] = v2; v4r[r][3] = v3;
            vv2[r] = v0 * v0 + v1 * v1 + v2 * v2 + v3 * v3;
        }
        block_reduce8<2>(vv2, redbuf);

        #pragma unroll
        for (int r = 0; r < 2; r++) {
            int b = b0 + r;
            float vn = fmaxf(sqrtf(vv2[r]), EPSF);
            float th = fast_tanh(vn);
            float kk = th / vn;
            float s  = kk * XSC;
            __half2 h01 = __floats2half2_rn(v4r[r][0] * s, v4r[r][1] * s);
            __half2 h23 = __floats2half2_rn(v4r[r][2] * s, v4r[r][3] * s);
            uint2 pk;
            pk.x = *reinterpret_cast<uint32_t*>(&h01);
            pk.y = *reinterpret_cast<uint32_t*>(&h23);
            *reinterpret_cast<uint2*>(&hs[(size_t)b * KR + tid * 4]) = pk;
            if (t == TT - 1) {
                float4 o4 = make_float4(kk * v4r[r][0], kk * v4r[r][1],
                                        kk * v4r[r][2], kk * v4r[r][3]);
                *reinterpret_cast<float4*>(&out[(size_t)b * HH + tid * 4]) = o4;
            }
            hn_loc[r] = fmaxf(th, EPSF);
        }
        group_barrier(y);
    }
}

// ---------------- launch ----------------
extern "C" void kernel_launch(void* const* d_in, const int* in_sizes, int n_in,
                              void* d_out, int out_size)
{
    const float* inp  = (const float*)d_in[0];   // [B,T,E]
    const float* W_ih = (const float*)d_in[1];   // [E,H]
    const float* W_hh = (const float*)d_in[2];   // [H,H]
    const float* b_h  = (const float*)d_in[3];   // [H]
    float* out = (float*)d_out;                  // [B,H]

    __half *Xs, *WihT, *WhhT, *hs;
    float *prem, *mh, *xn;
    cudaGetSymbolAddress((void**)&Xs,   g_Xs);
    cudaGetSymbolAddress((void**)&WihT, g_WihT);
    cudaGetSymbolAddress((void**)&WhhT, g_WhhT);
    cudaGetSymbolAddress((void**)&hs,   g_hs);
    cudaGetSymbolAddress((void**)&prem, g_prem);
    cudaGetSymbolAddress((void**)&mh,   g_mh);
    cudaGetSymbolAddress((void**)&xn,   g_xn);

    const int SMEM_BIG = 3 * (128 + 128) * 128;            // 96 KB (3 stages)
    const int SMEM_REC = 8 * 128 * 128 + 8 * 32 * 128;     // 128KB + 32KB = 160 KB
    cudaFuncSetAttribute(big_gemm_kernel,
                         cudaFuncAttributeMaxDynamicSharedMemorySize, SMEM_BIG);
    cudaFuncSetAttribute(recurrence_kernel,
                         cudaFuncAttributeMaxDynamicSharedMemorySize, SMEM_REC);

    // init hidden = 0
    {
        int n = (int)((size_t)BB * KR / 2);
        init_kernel<<<(n + 255) / 256, 256>>>((uint32_t*)hs);
    }

    // prep: weight transposes + X scale/norms (all hi-only fp16)
    {
        dim3 gw(HH / 32, HH / 32);
        splitW_kernel<<<gw, 256>>>(W_ih, WihT);
        splitW_kernel<<<gw, 256>>>(W_hh, WhhT);
        splitX_kernel<<<BB * TT, 256>>>(inp, Xs, xn);
    }

    // big GEMM: raw prem = Xs @ WihT^T  [32768, 1024], K=1024
    {
        dim3 grid(HH / 128, (BB * TT) / 128);
        big_gemm_kernel<<<grid, 256, SMEM_BIG>>>(Xs, WihT, prem);
    }

    // persistent recurrence: one kernel for all 128 steps
    recurrence_kernel<<<128, 256, SMEM_REC>>>(WhhT, prem, b_h, xn, hs, mh, out);
}